// round 2
// baseline (speedup 1.0000x reference)
#include <cuda_runtime.h>
#include <cuda_fp16.h>
#include <cstdint>
#include <math.h>

#define KC 16
#define DIM 128
#define TILE_M 128
#define NBATCH 65536
#define NTILES (NBATCH / TILE_M)

// -0.5 * 128 * log(2*pi)
#define LOG2PI_FACTOR (-117.619071363423756f)

// ---------------- device scratch (no allocations allowed) ----------------
__device__ __half g_Wh[KC * DIM * DIM];   // fp16 L, row n = k*128 + i, row-major [n][k]
__device__ float  g_c[KC * DIM];          // c[k][i] = sum_j half(L[k,i,j]) * mu[k,j]
__device__ float  g_cst[KC];              // logw + log2pi + logdet

// ---------------- helpers ----------------
static __device__ __forceinline__ uint32_t s2u(const void* p) {
    return (uint32_t)__cvta_generic_to_shared(p);
}
static __device__ __forceinline__ uint32_t f2h2(float a, float b) {
    __half2 h = __floats2half2_rn(a, b);
    return *reinterpret_cast<uint32_t*>(&h);
}

#define CP_ASYNC16(dst, src) \
    asm volatile("cp.async.cg.shared.global [%0], [%1], 16;" :: "r"(dst), "l"(src) : "memory")
#define CP_COMMIT() asm volatile("cp.async.commit_group;" ::: "memory")
#define CP_WAIT1() asm volatile("cp.async.wait_group 1;" ::: "memory")
#define CP_WAIT0() asm volatile("cp.async.wait_group 0;" ::: "memory")

#define LDSM_X4(r, a) \
    asm volatile("ldmatrix.sync.aligned.m8n8.x4.shared.b16 {%0,%1,%2,%3}, [%4];" \
        : "=r"((r)[0]), "=r"((r)[1]), "=r"((r)[2]), "=r"((r)[3]) : "r"(a))

static __device__ __forceinline__ void mma16816(float* d, const uint32_t* a,
                                                uint32_t b0, uint32_t b1) {
    asm volatile(
        "mma.sync.aligned.m16n8k16.row.col.f32.f16.f16.f32 "
        "{%0,%1,%2,%3}, {%4,%5,%6,%7}, {%8,%9}, {%0,%1,%2,%3};"
        : "+f"(d[0]), "+f"(d[1]), "+f"(d[2]), "+f"(d[3])
        : "r"(a[0]), "r"(a[1]), "r"(a[2]), "r"(a[3]), "r"(b0), "r"(b1));
}

// ---------------- smem layout ----------------
// W rows padded to 136 halves (272 B) for conflict-free ldmatrix
#define W_ROW_B   272
#define W_BUF_B   (DIM * W_ROW_B)        /* 34816 */
#define OFF_W0    0
#define OFF_W1    W_BUF_B
#define OFF_C     (2 * W_BUF_B)          /* 69632 */
#define OFF_CST   (OFF_C + KC * DIM * 4) /* 77824 */
#define SMEM_DYN  (OFF_CST + 64)         /* 77888 */

// ---------------- prepass: fp16 W, c, consts ----------------
__global__ void prep_comp_kernel(const float* __restrict__ prec,
                                 const float* __restrict__ means,
                                 const float* __restrict__ logw) {
    int k = blockIdx.x;       // 16 blocks
    int i = threadIdx.x;      // 128 threads
    const float* L = prec + ((size_t)k * DIM + i) * DIM;
    const float* mu = means + k * DIM;
    __half* wrow = g_Wh + ((size_t)k * DIM + i) * DIM;
    float cc = 0.f;
    #pragma unroll 8
    for (int j4 = 0; j4 < DIM / 4; j4++) {
        float4 v = ((const float4*)L)[j4];
        __half2 h0 = __floats2half2_rn(v.x, v.y);
        __half2 h1 = __floats2half2_rn(v.z, v.w);
        ((__half2*)wrow)[2 * j4]     = h0;
        ((__half2*)wrow)[2 * j4 + 1] = h1;
        float2 f0 = __half22float2(h0);
        float2 f1 = __half22float2(h1);
        cc = fmaf(f0.x, mu[4 * j4 + 0], cc);
        cc = fmaf(f0.y, mu[4 * j4 + 1], cc);
        cc = fmaf(f1.x, mu[4 * j4 + 2], cc);
        cc = fmaf(f1.y, mu[4 * j4 + 3], cc);
    }
    g_c[k * DIM + i] = cc;
    __shared__ float red[DIM];
    red[i] = logf(L[i]);      // diag element (i,i)
    __syncthreads();
    if (i == 0) {
        float s = 0.f;
        for (int j = 0; j < DIM; j++) s += red[j];
        g_cst[k] = logw[k] + LOG2PI_FACTOR + s;
    }
}

// ---------------- W tile producer (cp.async) ----------------
static __device__ __forceinline__ void issue_w(uint32_t ws_dst_base, int k, int tid) {
    const __half* src = g_Wh + (size_t)k * (DIM * DIM);
    #pragma unroll
    for (int it = 0; it < 16; it++) {
        int idx = tid + it * 128;         // 2048 chunks of 16B
        int r = idx >> 4, j = idx & 15;
        uint32_t dst = ws_dst_base + (uint32_t)(r * W_ROW_B + j * 16);
        CP_ASYNC16(dst, src + r * DIM + j * 8);
    }
    CP_COMMIT();
}

// ---------------- main fused kernel ----------------
__global__ void __launch_bounds__(128, 2)
gmm_main_kernel(const float* __restrict__ x, float* __restrict__ out) {
    extern __shared__ __align__(16) char smem[];
    uint32_t sb = s2u(smem);
    int tid = threadIdx.x;
    int w = tid >> 5;
    int l = tid & 31;
    int tile = blockIdx.x;

    // prefetch component 0 into buf0
    issue_w(sb + OFF_W0, 0, tid);

    // stage c / consts
    float* c_s = (float*)(smem + OFF_C);
    float* cst_s = (float*)(smem + OFF_CST);
    for (int i = tid; i < KC * DIM; i += 128) c_s[i] = g_c[i];
    if (tid < KC) cst_s[tid] = g_cst[tid];

    // ---- load A fragments once (X stays in registers for all 16 components) ----
    uint32_t A[2][8][4];
    {
        int c0 = (l & 3) * 2;
        #pragma unroll
        for (int mt = 0; mt < 2; mt++) {
            const float* xr0 = x + ((size_t)tile * TILE_M + w * 32 + mt * 16 + (l >> 2)) * DIM;
            const float* xr1 = xr0 + 8 * DIM;
            #pragma unroll
            for (int kt = 0; kt < 8; kt++) {
                int c = kt * 16 + c0;
                float2 v00 = *(const float2*)(xr0 + c);
                float2 v10 = *(const float2*)(xr1 + c);
                float2 v01 = *(const float2*)(xr0 + c + 8);
                float2 v11 = *(const float2*)(xr1 + c + 8);
                A[mt][kt][0] = f2h2(v00.x, v00.y);
                A[mt][kt][1] = f2h2(v10.x, v10.y);
                A[mt][kt][2] = f2h2(v01.x, v01.y);
                A[mt][kt][3] = f2h2(v11.x, v11.y);
            }
        }
    }

    // ldmatrix lane address components (x4: m0=rows+0/klo, m1=rows+0/khi, m2=rows+8/klo, m3=rows+8/khi)
    int m = l >> 3, rr = l & 7;
    uint32_t nrow_off = (uint32_t)(((m >> 1) & 1) * 8 + rr);
    uint32_t koff = (uint32_t)((m & 1) * 16);   // bytes

    float mx[4], s[4];
    #pragma unroll
    for (int j = 0; j < 4; j++) { mx[j] = -INFINITY; s[j] = 0.f; }

    for (int k = 0; k < KC; k++) {
        if (k < KC - 1) {
            issue_w(sb + (((k + 1) & 1) ? OFF_W1 : OFF_W0), k + 1, tid);
            CP_WAIT1();
        } else {
            CP_WAIT0();
        }
        __syncthreads();

        uint32_t wsb = sb + ((k & 1) ? OFF_W1 : OFF_W0);
        float ra[4] = {0.f, 0.f, 0.f, 0.f};

        #pragma unroll
        for (int h = 0; h < 2; h++) {
            float acc[2][8][4];
            #pragma unroll
            for (int mt = 0; mt < 2; mt++)
                #pragma unroll
                for (int nt = 0; nt < 8; nt++)
                    #pragma unroll
                    for (int j = 0; j < 4; j++) acc[mt][nt][j] = 0.f;

            #pragma unroll
            for (int kt = 0; kt < 8; kt++) {
                uint32_t b[4][4];
                #pragma unroll
                for (int pb = 0; pb < 4; pb++) {
                    uint32_t addr = wsb +
                        (uint32_t)((h * 64 + pb * 16) + nrow_off) * W_ROW_B +
                        koff + (uint32_t)(kt * 32);
                    LDSM_X4(b[pb], addr);
                }
                #pragma unroll
                for (int pb = 0; pb < 4; pb++) {
                    #pragma unroll
                    for (int sub = 0; sub < 2; sub++) {
                        int nt = pb * 2 + sub;
                        uint32_t b0 = b[pb][sub * 2 + 0];
                        uint32_t b1 = b[pb][sub * 2 + 1];
                        mma16816(acc[0][nt], A[0][kt], b0, b1);
                        mma16816(acc[1][nt], A[1][kt], b0, b1);
                    }
                }
            }

            // fused epilogue: Σ (y - c)^2 per row
            const float* crow = c_s + k * DIM + h * 64;
            #pragma unroll
            for (int nt = 0; nt < 8; nt++) {
                float2 cc = *(const float2*)(crow + nt * 8 + (l & 3) * 2);
                #pragma unroll
                for (int mt = 0; mt < 2; mt++) {
                    float d0 = acc[mt][nt][0] - cc.x;
                    float d1 = acc[mt][nt][1] - cc.y;
                    float d2 = acc[mt][nt][2] - cc.x;
                    float d3 = acc[mt][nt][3] - cc.y;
                    ra[mt * 2 + 0] = fmaf(d0, d0, fmaf(d1, d1, ra[mt * 2 + 0]));
                    ra[mt * 2 + 1] = fmaf(d2, d2, fmaf(d3, d3, ra[mt * 2 + 1]));
                }
            }
        }

        // quad-reduce across the 4 lanes sharing each row, then online logsumexp
        float ck = cst_s[k];
        #pragma unroll
        for (int j = 0; j < 4; j++) {
            float v = ra[j];
            v += __shfl_xor_sync(0xffffffff, v, 1);
            v += __shfl_xor_sync(0xffffffff, v, 2);
            float mval = ck - 0.5f * v;
            if (mval > mx[j]) { s[j] = s[j] * __expf(mx[j] - mval) + 1.f; mx[j] = mval; }
            else              { s[j] += __expf(mval - mx[j]); }
        }
        __syncthreads();   // protect buffer (k&1) before it is refilled at iter k+1
    }

    if ((l & 3) == 0) {
        #pragma unroll
        for (int mt = 0; mt < 2; mt++)
            #pragma unroll
            for (int pr = 0; pr < 2; pr++) {
                int row = tile * TILE_M + w * 32 + mt * 16 + pr * 8 + (l >> 2);
                int j = mt * 2 + pr;
                out[row] = mx[j] + logf(s[j]);
            }
    }
}

// ---------------- launch ----------------
extern "C" void kernel_launch(void* const* d_in, const int* in_sizes, int n_in,
                              void* d_out, int out_size) {
    const float* x     = (const float*)d_in[0];
    const float* means = (const float*)d_in[1];
    const float* prec  = (const float*)d_in[2];
    const float* logw  = (const float*)d_in[3];
    float* out = (float*)d_out;

    cudaFuncSetAttribute(gmm_main_kernel, cudaFuncAttributeMaxDynamicSharedMemorySize, SMEM_DYN);

    prep_comp_kernel<<<KC, DIM>>>(prec, means, logw);
    gmm_main_kernel<<<NTILES, 128, SMEM_DYN>>>(x, out);
}

// round 3
// speedup vs baseline: 1.0254x; 1.0254x over previous
#include <cuda_runtime.h>
#include <cuda_fp16.h>
#include <cstdint>
#include <math.h>

#define KC 16
#define DIM 128
#define TILE_M 128
#define NBATCH 65536
#define NTILES (NBATCH / TILE_M)

// -0.5 * 128 * log(2*pi)
#define LOG2PI_FACTOR (-117.619071363423756f)

// ---------------- device scratch (no allocations allowed) ----------------
__device__ __half g_Wh[KC * DIM * DIM];   // fp16 L, row n = k*128 + i
__device__ float  g_c[KC * DIM];          // c[k][i] = sum_j half(L[k,i,j]) * mu[k,j]
__device__ float  g_cst[KC];              // logw + log2pi + logdet

// ---------------- helpers ----------------
static __device__ __forceinline__ uint32_t s2u(const void* p) {
    return (uint32_t)__cvta_generic_to_shared(p);
}
static __device__ __forceinline__ uint32_t f2h2(float a, float b) {
    __half2 h = __floats2half2_rn(a, b);
    return *reinterpret_cast<uint32_t*>(&h);
}

#define CP_ASYNC16(dst, src) \
    asm volatile("cp.async.cg.shared.global [%0], [%1], 16;" :: "r"(dst), "l"(src) : "memory")
#define CP_COMMIT() asm volatile("cp.async.commit_group;" ::: "memory")
#define CP_WAIT0() asm volatile("cp.async.wait_group 0;" ::: "memory")

#define LDSM_X4(r, a) \
    asm volatile("ldmatrix.sync.aligned.m8n8.x4.shared.b16 {%0,%1,%2,%3}, [%4];" \
        : "=r"((r)[0]), "=r"((r)[1]), "=r"((r)[2]), "=r"((r)[3]) : "r"(a))

static __device__ __forceinline__ void mma16816(float* d, const uint32_t* a,
                                                uint32_t b0, uint32_t b1) {
    asm volatile(
        "mma.sync.aligned.m16n8k16.row.col.f32.f16.f16.f32 "
        "{%0,%1,%2,%3}, {%4,%5,%6,%7}, {%8,%9}, {%0,%1,%2,%3};"
        : "+f"(d[0]), "+f"(d[1]), "+f"(d[2]), "+f"(d[3])
        : "r"(a[0]), "r"(a[1]), "r"(a[2]), "r"(a[3]), "r"(b0), "r"(b1));
}

// ---------------- smem layout ----------------
// W rows padded to 136 halves (272 B) for conflict-free ldmatrix
#define W_ROW_B   272
#define HBUF_B    (64 * W_ROW_B)          /* 17408: half-component (64 N-rows) */
#define OFF_W0    0
#define OFF_W1    HBUF_B
#define OFF_C     (2 * HBUF_B)            /* 34816 */
#define OFF_CST   (OFF_C + KC * DIM * 4)  /* 43008 */
#define SMEM_DYN  (OFF_CST + 64)          /* 43072 -> 4 CTAs/SM */

// ---------------- prepass: fp16 W, c, consts ----------------
__global__ void prep_comp_kernel(const float* __restrict__ prec,
                                 const float* __restrict__ means,
                                 const float* __restrict__ logw) {
    int k = blockIdx.x;       // 16 blocks
    int i = threadIdx.x;      // 128 threads
    const float* L = prec + ((size_t)k * DIM + i) * DIM;
    const float* mu = means + k * DIM;
    __half* wrow = g_Wh + ((size_t)k * DIM + i) * DIM;
    float cc = 0.f;
    #pragma unroll 8
    for (int j4 = 0; j4 < DIM / 4; j4++) {
        float4 v = ((const float4*)L)[j4];
        __half2 h0 = __floats2half2_rn(v.x, v.y);
        __half2 h1 = __floats2half2_rn(v.z, v.w);
        ((__half2*)wrow)[2 * j4]     = h0;
        ((__half2*)wrow)[2 * j4 + 1] = h1;
        float2 f0 = __half22float2(h0);
        float2 f1 = __half22float2(h1);
        cc = fmaf(f0.x, mu[4 * j4 + 0], cc);
        cc = fmaf(f0.y, mu[4 * j4 + 1], cc);
        cc = fmaf(f1.x, mu[4 * j4 + 2], cc);
        cc = fmaf(f1.y, mu[4 * j4 + 3], cc);
    }
    g_c[k * DIM + i] = cc;
    __shared__ float red[DIM];
    red[i] = logf(L[i]);      // diag element (i,i)
    __syncthreads();
    if (i == 0) {
        float s = 0.f;
        for (int j = 0; j < DIM; j++) s += red[j];
        g_cst[k] = logw[k] + LOG2PI_FACTOR + s;
    }
}

// ---------------- W half-tile producer (cp.async, 64 rows) ----------------
static __device__ __forceinline__ void issue_w_half(uint32_t dst_base, int hc, int tid) {
    const __half* src = g_Wh + (size_t)(hc >> 1) * (DIM * DIM) + (size_t)(hc & 1) * 64 * DIM;
    #pragma unroll
    for (int it = 0; it < 8; it++) {
        int idx = tid + it * 128;         // 1024 chunks of 16B
        int r = idx >> 4, j = idx & 15;
        uint32_t dst = dst_base + (uint32_t)(r * W_ROW_B + j * 16);
        CP_ASYNC16(dst, src + r * DIM + j * 8);
    }
    CP_COMMIT();
}

// ---------------- main fused kernel ----------------
__global__ void __launch_bounds__(128, 4)
gmm_main_kernel(const float* __restrict__ x, float* __restrict__ out) {
    extern __shared__ __align__(16) char smem[];
    uint32_t sb = s2u(smem);
    int tid = threadIdx.x;
    int w = tid >> 5;
    int l = tid & 31;
    int tile = blockIdx.x;

    // prefetch half-component 0 into buf0
    issue_w_half(sb + OFF_W0, 0, tid);

    // stage c / consts (ordered by the __syncthreads at top of iter 0)
    float* c_s = (float*)(smem + OFF_C);
    float* cst_s = (float*)(smem + OFF_CST);
    for (int i = tid; i < KC * DIM; i += 128) c_s[i] = g_c[i];
    if (tid < KC) cst_s[tid] = g_cst[tid];

    // ---- load A fragments once (X stays in registers for all 16 components) ----
    uint32_t A[2][8][4];
    {
        int c0 = (l & 3) * 2;
        #pragma unroll
        for (int mt = 0; mt < 2; mt++) {
            const float* xr0 = x + ((size_t)tile * TILE_M + w * 32 + mt * 16 + (l >> 2)) * DIM;
            const float* xr1 = xr0 + 8 * DIM;
            #pragma unroll
            for (int kt = 0; kt < 8; kt++) {
                int c = kt * 16 + c0;
                float2 v00 = *(const float2*)(xr0 + c);
                float2 v10 = *(const float2*)(xr1 + c);
                float2 v01 = *(const float2*)(xr0 + c + 8);
                float2 v11 = *(const float2*)(xr1 + c + 8);
                A[mt][kt][0] = f2h2(v00.x, v00.y);
                A[mt][kt][1] = f2h2(v10.x, v10.y);
                A[mt][kt][2] = f2h2(v01.x, v01.y);
                A[mt][kt][3] = f2h2(v11.x, v11.y);
            }
        }
    }

    // ldmatrix lane address components
    int m = l >> 3, rr = l & 7;
    uint32_t nrow_off = (uint32_t)(((m >> 1) & 1) * 8 + rr);
    uint32_t koff = (uint32_t)((m & 1) * 16);   // bytes

    float mx[4], s[4], ra[4];
    #pragma unroll
    for (int j = 0; j < 4; j++) { mx[j] = -INFINITY; s[j] = 0.f; }

    for (int hc = 0; hc < 2 * KC; hc++) {
        int k = hc >> 1;
        CP_WAIT0();
        __syncthreads();   // buf(hc) visible to all; all warps done with buf(hc-1)
        if (hc + 1 < 2 * KC)
            issue_w_half(sb + (((hc + 1) & 1) ? OFF_W1 : OFF_W0), hc + 1, tid);

        uint32_t wsb = sb + ((hc & 1) ? OFF_W1 : OFF_W0);
        if ((hc & 1) == 0) {
            #pragma unroll
            for (int j = 0; j < 4; j++) ra[j] = 0.f;
        }

        #pragma unroll
        for (int nc = 0; nc < 2; nc++) {
            float acc[2][4][4];
            #pragma unroll
            for (int mt = 0; mt < 2; mt++)
                #pragma unroll
                for (int nt = 0; nt < 4; nt++)
                    #pragma unroll
                    for (int j = 0; j < 4; j++) acc[mt][nt][j] = 0.f;

            #pragma unroll
            for (int kt = 0; kt < 8; kt++) {
                uint32_t b[2][4];
                #pragma unroll
                for (int pb = 0; pb < 2; pb++) {
                    uint32_t addr = wsb +
                        (uint32_t)((nc * 32 + pb * 16) + nrow_off) * W_ROW_B +
                        koff + (uint32_t)(kt * 32);
                    LDSM_X4(b[pb], addr);
                }
                #pragma unroll
                for (int pb = 0; pb < 2; pb++) {
                    #pragma unroll
                    for (int sub = 0; sub < 2; sub++) {
                        int nt = pb * 2 + sub;
                        uint32_t b0 = b[pb][sub * 2 + 0];
                        uint32_t b1 = b[pb][sub * 2 + 1];
                        mma16816(acc[0][nt], A[0][kt], b0, b1);
                        mma16816(acc[1][nt], A[1][kt], b0, b1);
                    }
                }
            }

            // fused epilogue: Σ (y - c)^2 for these 32 columns
            const float* crow = c_s + k * DIM + (hc & 1) * 64 + nc * 32;
            #pragma unroll
            for (int nt = 0; nt < 4; nt++) {
                float2 cc = *(const float2*)(crow + nt * 8 + (l & 3) * 2);
                #pragma unroll
                for (int mt = 0; mt < 2; mt++) {
                    float d0 = acc[mt][nt][0] - cc.x;
                    float d1 = acc[mt][nt][1] - cc.y;
                    float d2 = acc[mt][nt][2] - cc.x;
                    float d3 = acc[mt][nt][3] - cc.y;
                    ra[mt * 2 + 0] = fmaf(d0, d0, fmaf(d1, d1, ra[mt * 2 + 0]));
                    ra[mt * 2 + 1] = fmaf(d2, d2, fmaf(d3, d3, ra[mt * 2 + 1]));
                }
            }
        }

        if (hc & 1) {
            // component complete: quad-reduce, then online logsumexp
            float ck = cst_s[k];
            #pragma unroll
            for (int j = 0; j < 4; j++) {
                float v = ra[j];
                v += __shfl_xor_sync(0xffffffff, v, 1);
                v += __shfl_xor_sync(0xffffffff, v, 2);
                float mval = ck - 0.5f * v;
                if (mval > mx[j]) { s[j] = s[j] * __expf(mx[j] - mval) + 1.f; mx[j] = mval; }
                else              { s[j] += __expf(mval - mx[j]); }
            }
        }
    }

    if ((l & 3) == 0) {
        #pragma unroll
        for (int mt = 0; mt < 2; mt++)
            #pragma unroll
            for (int pr = 0; pr < 2; pr++) {
                int row = tile * TILE_M + w * 32 + mt * 16 + pr * 8 + (l >> 2);
                int j = mt * 2 + pr;
                out[row] = mx[j] + logf(s[j]);
            }
    }
}

// ---------------- launch ----------------
extern "C" void kernel_launch(void* const* d_in, const int* in_sizes, int n_in,
                              void* d_out, int out_size) {
    const float* x     = (const float*)d_in[0];
    const float* means = (const float*)d_in[1];
    const float* prec  = (const float*)d_in[2];
    const float* logw  = (const float*)d_in[3];
    float* out = (float*)d_out;

    cudaFuncSetAttribute(gmm_main_kernel, cudaFuncAttributeMaxDynamicSharedMemorySize, SMEM_DYN);

    prep_comp_kernel<<<KC, DIM>>>(prec, means, logw);
    gmm_main_kernel<<<NTILES, 128, SMEM_DYN>>>(x, out);
}

// round 4
// speedup vs baseline: 1.4591x; 1.4230x over previous
#include <cuda_runtime.h>
#include <cuda_fp16.h>
#include <cstdint>
#include <math.h>

#define KC 16
#define DIM 128
#define TILE_M 128
#define NBATCH 65536
#define NTILES (NBATCH / TILE_M)

// -0.5 * 128 * log(2*pi)
#define LOG2PI_FACTOR (-117.619071363423756f)

// ---------------- device scratch (no allocations allowed) ----------------
__device__ __half g_Wh[KC * DIM * DIM];   // fp16 L, row n = k*128 + i
__device__ float  g_c[KC * DIM];          // c[k][i] = sum_j half(L[k,i,j]) * mu[k,j]
__device__ float  g_cst[KC];              // logw + log2pi + logdet

// ---------------- helpers ----------------
static __device__ __forceinline__ uint32_t s2u(const void* p) {
    return (uint32_t)__cvta_generic_to_shared(p);
}
static __device__ __forceinline__ uint32_t f2h2(float a, float b) {
    __half2 h = __floats2half2_rn(a, b);
    return *reinterpret_cast<uint32_t*>(&h);
}

#define CP_ASYNC16_Z(dst, src, sz) \
    asm volatile("cp.async.cg.shared.global [%0], [%1], 16, %2;" \
                 :: "r"(dst), "l"(src), "r"(sz) : "memory")
#define CP_COMMIT() asm volatile("cp.async.commit_group;" ::: "memory")
#define CP_WAIT0() asm volatile("cp.async.wait_group 0;" ::: "memory")

#define LDSM_X4(r, a) \
    asm volatile("ldmatrix.sync.aligned.m8n8.x4.shared.b16 {%0,%1,%2,%3}, [%4];" \
        : "=r"((r)[0]), "=r"((r)[1]), "=r"((r)[2]), "=r"((r)[3]) : "r"(a))

static __device__ __forceinline__ void mma16816(float* d, const uint32_t* a,
                                                uint32_t b0, uint32_t b1) {
    asm volatile(
        "mma.sync.aligned.m16n8k16.row.col.f32.f16.f16.f32 "
        "{%0,%1,%2,%3}, {%4,%5,%6,%7}, {%8,%9}, {%0,%1,%2,%3};"
        : "+f"(d[0]), "+f"(d[1]), "+f"(d[2]), "+f"(d[3])
        : "r"(a[0]), "r"(a[1]), "r"(a[2]), "r"(a[3]), "r"(b0), "r"(b1));
}

// ---------------- smem layout ----------------
// W rows padded to 136 halves (272 B) for conflict-free ldmatrix
#define W_ROW_B   272
#define HBUF_B    (64 * W_ROW_B)          /* 17408: half-component (64 N-rows) */
#define OFF_W0    0
#define OFF_W1    HBUF_B
#define OFF_C     (2 * HBUF_B)            /* 34816 */
#define OFF_CST   (OFF_C + KC * DIM * 4)  /* 43008 */
#define SMEM_DYN  (OFF_CST + 64)          /* 43072 -> 4 CTAs/SM */

// ---------------- prepass: fp16 W, c, consts ----------------
__global__ void prep_comp_kernel(const float* __restrict__ prec,
                                 const float* __restrict__ means,
                                 const float* __restrict__ logw) {
    int k = blockIdx.x;       // 16 blocks
    int i = threadIdx.x;      // 128 threads
    const float* L = prec + ((size_t)k * DIM + i) * DIM;
    const float* mu = means + k * DIM;
    __half* wrow = g_Wh + ((size_t)k * DIM + i) * DIM;
    float cc = 0.f;
    #pragma unroll 8
    for (int j4 = 0; j4 < DIM / 4; j4++) {
        float4 v = ((const float4*)L)[j4];
        __half2 h0 = __floats2half2_rn(v.x, v.y);
        __half2 h1 = __floats2half2_rn(v.z, v.w);
        ((__half2*)wrow)[2 * j4]     = h0;
        ((__half2*)wrow)[2 * j4 + 1] = h1;
        float2 f0 = __half22float2(h0);
        float2 f1 = __half22float2(h1);
        cc = fmaf(f0.x, mu[4 * j4 + 0], cc);
        cc = fmaf(f0.y, mu[4 * j4 + 1], cc);
        cc = fmaf(f1.x, mu[4 * j4 + 2], cc);
        cc = fmaf(f1.y, mu[4 * j4 + 3], cc);
    }
    g_c[k * DIM + i] = cc;
    __shared__ float red[DIM];
    red[i] = logf(L[i]);      // diag element (i,i)
    __syncthreads();
    if (i == 0) {
        float s = 0.f;
        for (int j = 0; j < DIM; j++) s += red[j];
        g_cst[k] = logw[k] + LOG2PI_FACTOR + s;
    }
}

// ---------------- W half-tile producer (cp.async + triangular zfill) -------
static __device__ __forceinline__ void issue_w_half(uint32_t dst_base, int hc, int tid) {
    int half = hc & 1;
    const __half* src = g_Wh + (size_t)(hc >> 1) * (DIM * DIM) + (size_t)half * 64 * DIM;
    int rbase = half * 64;
    #pragma unroll
    for (int it = 0; it < 8; it++) {
        int idx = tid + it * 128;         // 1024 chunks of 16B
        int r = idx >> 4, j = idx & 15;
        uint32_t dst = dst_base + (uint32_t)(r * W_ROW_B + j * 16);
        // chunk j covers cols 8j..8j+7 of global row rbase+r; fully above diag -> zero-fill
        int sz = (8 * j <= rbase + r) ? 16 : 0;
        CP_ASYNC16_Z(dst, src + r * DIM + j * 8, sz);
    }
    CP_COMMIT();
}

// ---------------- triangular half-component compute ----------------
template <int BASEG>
static __device__ __forceinline__ void process_half(
    uint32_t wsb, const float* crow_base, const uint32_t (&A)[2][8][4],
    float* ra, uint32_t nrow_off, uint32_t koff, int l)
{
    #pragma unroll
    for (int pg = 0; pg < 4; pg++) {
        const int g = BASEG + pg;            // global 16-col group 0..7
        float acc[2][2][4];
        #pragma unroll
        for (int mt = 0; mt < 2; mt++)
            #pragma unroll
            for (int sub = 0; sub < 2; sub++)
                #pragma unroll
                for (int j = 0; j < 4; j++) acc[mt][sub][j] = 0.f;

        #pragma unroll
        for (int kt = 0; kt <= g; kt++) {    // lower-triangular: only kt <= g
            uint32_t b[4];
            uint32_t addr = wsb + (uint32_t)(pg * 16 + nrow_off) * W_ROW_B +
                            koff + (uint32_t)(kt * 32);
            LDSM_X4(b, addr);
            mma16816(acc[0][0], A[0][kt], b[0], b[1]);
            mma16816(acc[0][1], A[0][kt], b[2], b[3]);
            mma16816(acc[1][0], A[1][kt], b[0], b[1]);
            mma16816(acc[1][1], A[1][kt], b[2], b[3]);
        }

        // fused epilogue: Σ (y - c)^2 for these 16 columns
        const float* crow = crow_base + g * 16;
        #pragma unroll
        for (int sub = 0; sub < 2; sub++) {
            float2 cc = *(const float2*)(crow + sub * 8 + (l & 3) * 2);
            #pragma unroll
            for (int mt = 0; mt < 2; mt++) {
                float d0 = acc[mt][sub][0] - cc.x;
                float d1 = acc[mt][sub][1] - cc.y;
                float d2 = acc[mt][sub][2] - cc.x;
                float d3 = acc[mt][sub][3] - cc.y;
                ra[mt * 2 + 0] = fmaf(d0, d0, fmaf(d1, d1, ra[mt * 2 + 0]));
                ra[mt * 2 + 1] = fmaf(d2, d2, fmaf(d3, d3, ra[mt * 2 + 1]));
            }
        }
    }
}

// ---------------- main fused kernel ----------------
__global__ void __launch_bounds__(128, 4)
gmm_main_kernel(const float* __restrict__ x, float* __restrict__ out) {
    extern __shared__ __align__(16) char smem[];
    uint32_t sb = s2u(smem);
    int tid = threadIdx.x;
    int w = tid >> 5;
    int l = tid & 31;
    int tile = blockIdx.x;

    // prefetch half-component 0 into buf0
    issue_w_half(sb + OFF_W0, 0, tid);

    // stage c / consts (ordered by the __syncthreads at top of iter 0)
    float* c_s = (float*)(smem + OFF_C);
    float* cst_s = (float*)(smem + OFF_CST);
    for (int i = tid; i < KC * DIM; i += 128) c_s[i] = g_c[i];
    if (tid < KC) cst_s[tid] = g_cst[tid];

    // ---- load A fragments once (X stays in registers for all 16 components) ----
    uint32_t A[2][8][4];
    {
        int c0 = (l & 3) * 2;
        #pragma unroll
        for (int mt = 0; mt < 2; mt++) {
            const float* xr0 = x + ((size_t)tile * TILE_M + w * 32 + mt * 16 + (l >> 2)) * DIM;
            const float* xr1 = xr0 + 8 * DIM;
            #pragma unroll
            for (int kt = 0; kt < 8; kt++) {
                int c = kt * 16 + c0;
                float2 v00 = *(const float2*)(xr0 + c);
                float2 v10 = *(const float2*)(xr1 + c);
                float2 v01 = *(const float2*)(xr0 + c + 8);
                float2 v11 = *(const float2*)(xr1 + c + 8);
                A[mt][kt][0] = f2h2(v00.x, v00.y);
                A[mt][kt][1] = f2h2(v10.x, v10.y);
                A[mt][kt][2] = f2h2(v01.x, v01.y);
                A[mt][kt][3] = f2h2(v11.x, v11.y);
            }
        }
    }

    // ldmatrix lane address components
    int m = l >> 3, rr = l & 7;
    uint32_t nrow_off = (uint32_t)(((m >> 1) & 1) * 8 + rr);
    uint32_t koff = (uint32_t)((m & 1) * 16);   // bytes

    float mx[4], s[4], ra[4];
    #pragma unroll
    for (int j = 0; j < 4; j++) { mx[j] = -INFINITY; s[j] = 0.f; }

    for (int hc = 0; hc < 2 * KC; hc++) {
        int k = hc >> 1;
        CP_WAIT0();
        __syncthreads();   // buf(hc) visible; all warps done reading buf(hc-1)
        if (hc + 1 < 2 * KC)
            issue_w_half(sb + (((hc + 1) & 1) ? OFF_W1 : OFF_W0), hc + 1, tid);

        uint32_t wsb = sb + ((hc & 1) ? OFF_W1 : OFF_W0);
        const float* crow_base = c_s + k * DIM;

        if ((hc & 1) == 0) {
            #pragma unroll
            for (int j = 0; j < 4; j++) ra[j] = 0.f;
            process_half<0>(wsb, crow_base, A, ra, nrow_off, koff, l);
        } else {
            process_half<4>(wsb, crow_base, A, ra, nrow_off, koff, l);
            // component complete: quad-reduce, then online logsumexp
            float ck = cst_s[k];
            #pragma unroll
            for (int j = 0; j < 4; j++) {
                float v = ra[j];
                v += __shfl_xor_sync(0xffffffff, v, 1);
                v += __shfl_xor_sync(0xffffffff, v, 2);
                float mval = ck - 0.5f * v;
                if (mval > mx[j]) { s[j] = s[j] * __expf(mx[j] - mval) + 1.f; mx[j] = mval; }
                else              { s[j] += __expf(mval - mx[j]); }
            }
        }
    }

    if ((l & 3) == 0) {
        #pragma unroll
        for (int mt = 0; mt < 2; mt++)
            #pragma unroll
            for (int pr = 0; pr < 2; pr++) {
                int row = tile * TILE_M + w * 32 + mt * 16 + pr * 8 + (l >> 2);
                int j = mt * 2 + pr;
                out[row] = mx[j] + logf(s[j]);
            }
    }
}

// ---------------- launch ----------------
extern "C" void kernel_launch(void* const* d_in, const int* in_sizes, int n_in,
                              void* d_out, int out_size) {
    const float* x     = (const float*)d_in[0];
    const float* means = (const float*)d_in[1];
    const float* prec  = (const float*)d_in[2];
    const float* logw  = (const float*)d_in[3];
    float* out = (float*)d_out;

    cudaFuncSetAttribute(gmm_main_kernel, cudaFuncAttributeMaxDynamicSharedMemorySize, SMEM_DYN);

    prep_comp_kernel<<<KC, DIM>>>(prec, means, logw);
    gmm_main_kernel<<<NTILES, 128, SMEM_DYN>>>(x, out);
}